// round 4
// baseline (speedup 1.0000x reference)
#include <cuda_runtime.h>
#include <cstddef>

// ---------------------------------------------------------------------------
// DeepSDSphere: 2-stage SRCNN-style pipeline.
// Round 2 change: conv5x5 64->32 inner loop converted to packed fma.rn.f32x2
// (FFMA2, 2 fp32 FMA per issue slot) with output channels packed in pairs.
// ---------------------------------------------------------------------------

#define B_   4
#define F_   64

typedef unsigned long long u64;

__device__ __forceinline__ u64 pack2(float lo, float hi) {
    u64 r;
    asm("mov.b64 %0, {%1, %2};" : "=l"(r) : "f"(lo), "f"(hi));
    return r;
}
__device__ __forceinline__ void fma2(u64& d, u64 a, u64 b) {
    asm("fma.rn.f32x2 %0, %1, %2, %0;" : "+l"(d) : "l"(a), "l"(b));
}
__device__ __forceinline__ float2 unpack2(u64 v) {
    float lo, hi;
    asm("mov.b64 {%0, %1}, %2;" : "=f"(lo), "=f"(hi) : "l"(v));
    return make_float2(lo, hi);
}

// scratch layout (floats)
#define SZ_A   (4u*64u*360u*720u)          // disco output   66,355,200
#define SZ_B2  (4u*32u*360u*720u)          // conv2 output   33,177,600
#define SZ_H   (4u*2u*360u*720u)           // concat input    2,073,600
#define SZ_Y1  (4u*180u*360u)              // stage1 result     259,200
#define OFF_A   0u
#define OFF_B2  (OFF_A + SZ_A)
#define OFF_H   (OFF_B2 + SZ_B2)
#define OFF_Y1  (OFF_H + SZ_H)
#define SCRATCH_FLOATS (OFF_Y1 + SZ_Y1)

__device__ float g_scratch[SCRATCH_FLOATS];

// ---------------------------------------------------------------------------
// Kernel 1: bilinear 2x upsample (half-pixel) + concat.
// ---------------------------------------------------------------------------
__global__ void upsample_concat_kernel(const float* __restrict__ x,
                                       const float* __restrict__ elev,
                                       float* __restrict__ out,
                                       int Hin, int Win)
{
    int H2 = Hin * 2, W2 = Win * 2;
    int total = B_ * H2 * W2;
    int idx = blockIdx.x * blockDim.x + threadIdx.x;
    if (idx >= total) return;
    int j = idx % W2;
    int t = idx / W2;
    int i = t % H2;
    int b = t / H2;

    float sy = (i + 0.5f) * 0.5f - 0.5f;
    sy = fminf(fmaxf(sy, 0.0f), (float)(Hin - 1));
    int r0 = (int)floorf(sy);
    int r1 = min(r0 + 1, Hin - 1);
    float ty = sy - (float)r0;

    float sx = (j + 0.5f) * 0.5f - 0.5f;
    sx = fminf(fmaxf(sx, 0.0f), (float)(Win - 1));
    int c0 = (int)floorf(sx);
    int c1 = min(c0 + 1, Win - 1);
    float tx = sx - (float)c0;

    const float* xb = x + (size_t)b * Hin * Win;
    float v00 = xb[r0 * Win + c0];
    float v01 = xb[r0 * Win + c1];
    float v10 = xb[r1 * Win + c0];
    float v11 = xb[r1 * Win + c1];
    float left  = v00 * (1.0f - ty) + v10 * ty;
    float right = v01 * (1.0f - ty) + v11 * ty;
    float v = left * (1.0f - tx) + right * tx;

    size_t plane = (size_t)H2 * W2;
    out[((size_t)b * 2 + 0) * plane + (size_t)i * W2 + j] = v;
    out[((size_t)b * 2 + 1) * plane + (size_t)i * W2 + j] =
        elev[(size_t)b * plane + (size_t)i * W2 + j];
}

// ---------------------------------------------------------------------------
// Kernel 2: disco conv (sparse gather conv) + bias + relu.
// ---------------------------------------------------------------------------
__global__ __launch_bounds__(256)
void disco_kernel(const float* __restrict__ h,
                  const int*   __restrict__ idx,
                  const float* __restrict__ val,
                  const float* __restrict__ w,
                  const float* __restrict__ bias,
                  float* __restrict__ out,
                  int P)
{
    __shared__ float w_s[F_ * 18];
    __shared__ float b_s[F_];
    for (int t = threadIdx.x; t < F_ * 18; t += 256) w_s[t] = w[t];
    if (threadIdx.x < F_) b_s[threadIdx.x] = bias[threadIdx.x];
    __syncthreads();

    int p = blockIdx.x * 256 + threadIdx.x;
    if (p >= P) return;

    int id[8];
    const int4* ip = reinterpret_cast<const int4*>(idx + (size_t)p * 8);
    int4 ia = ip[0], ib = ip[1];
    id[0]=ia.x; id[1]=ia.y; id[2]=ia.z; id[3]=ia.w;
    id[4]=ib.x; id[5]=ib.y; id[6]=ib.z; id[7]=ib.w;

    float v[9][8];
#pragma unroll
    for (int k = 0; k < 9; k++) {
        const float4* vp = reinterpret_cast<const float4*>(val + ((size_t)k * P + p) * 8);
        float4 a = vp[0], c = vp[1];
        v[k][0]=a.x; v[k][1]=a.y; v[k][2]=a.z; v[k][3]=a.w;
        v[k][4]=c.x; v[k][5]=c.y; v[k][6]=c.z; v[k][7]=c.w;
    }

    for (int b = 0; b < B_; b++) {
        const float* h0 = h + (size_t)(b * 2 + 0) * P;
        const float* h1 = h + (size_t)(b * 2 + 1) * P;
        float g0[8], g1[8];
#pragma unroll
        for (int n = 0; n < 8; n++) { g0[n] = h0[id[n]]; g1[n] = h1[id[n]]; }

        float z0[9], z1[9];
#pragma unroll
        for (int k = 0; k < 9; k++) {
            float s0 = 0.0f, s1 = 0.0f;
#pragma unroll
            for (int n = 0; n < 8; n++) {
                s0 = fmaf(g0[n], v[k][n], s0);
                s1 = fmaf(g1[n], v[k][n], s1);
            }
            z0[k] = s0; z1[k] = s1;
        }

        float* ob = out + (size_t)(b * F_) * P + p;
        for (int o = 0; o < F_; o++) {
            const float* wo = &w_s[o * 18];
            float a = b_s[o];
#pragma unroll
            for (int k = 0; k < 9; k++)
                a = fmaf(z0[k], wo[k], fmaf(z1[k], wo[9 + k], a));
            ob[(size_t)o * P] = fmaxf(a, 0.0f);
        }
    }
}

// ---------------------------------------------------------------------------
// Kernel 3: 5x5 SAME conv, IC=64 -> OC=32, bias + relu.  FFMA2 version.
// 32x16 pixel tile, 256 threads; thread = 4 pixels x 16 oc (8 packed pairs).
// ---------------------------------------------------------------------------
__global__ __launch_bounds__(256, 2)
void conv5x5_ic64_oc32_relu(const float* __restrict__ in,
                            const float* __restrict__ w,
                            const float* __restrict__ bias,
                            float* __restrict__ out,
                            int H, int W)
{
    const int TW = 32, TH = 16, ICC = 8, IC = 64, OC = 32;
    __shared__ __align__(16) float in_s[ICC][TH + 4][TW + 4];   // 23040 B
    __shared__ __align__(16) float w_s[ICC][25][OC];            // 25600 B

    int b  = blockIdx.z;
    int x0 = blockIdx.x * TW;
    int y0 = blockIdx.y * TH;
    int tid  = threadIdx.x;
    int slot = tid & 127;
    int ocg  = tid >> 7;          // 0 or 1
    int sx   = slot & 31;
    int sy   = slot >> 5;         // 0..3 -> rows sy*4 .. sy*4+3

    u64 acc[4][8];
#pragma unroll
    for (int i = 0; i < 4; i++)
#pragma unroll
        for (int j = 0; j < 8; j++) acc[i][j] = 0ull;

    for (int cc = 0; cc < IC; cc += ICC) {
        __syncthreads();
        const float* inb = in + ((size_t)b * IC + cc) * H * W;
        // stage input tile (with 2-halo, zero pad)
        for (int t = tid; t < ICC * (TH + 4) * (TW + 4); t += 256) {
            int ic  = t / ((TH + 4) * (TW + 4));
            int rem = t - ic * (TH + 4) * (TW + 4);
            int r = rem / (TW + 4);
            int c = rem - r * (TW + 4);
            int gy = y0 - 2 + r;
            int gx = x0 - 2 + c;
            float vv = 0.0f;
            if (gy >= 0 && gy < H && gx >= 0 && gx < W)
                vv = inb[(size_t)ic * H * W + (size_t)gy * W + gx];
            in_s[ic][r][c] = vv;
        }
        // stage weight chunk: w global layout (OC, IC, 5, 5)
        for (int t = tid; t < ICC * 25 * OC; t += 256) {
            int oc  = t / (ICC * 25);
            int rem = t - oc * (ICC * 25);
            int ic  = rem / 25;
            int tap = rem - ic * 25;
            w_s[ic][tap][oc] = w[((size_t)oc * IC + cc + ic) * 25 + tap];
        }
        __syncthreads();

#pragma unroll 1
        for (int ic = 0; ic < ICC; ic++) {
#pragma unroll 1
            for (int dy = 0; dy < 5; dy++) {
#pragma unroll
                for (int dx = 0; dx < 5; dx++) {
                    // 16 oc = 8 packed f32x2 weight pairs (broadcast LDS.128)
                    const u64* wrow = reinterpret_cast<const u64*>(
                        &w_s[ic][dy * 5 + dx][ocg * 16]);
                    u64 wv[8];
#pragma unroll
                    for (int j = 0; j < 8; j++) wv[j] = wrow[j];
#pragma unroll
                    for (int i = 0; i < 4; i++) {
                        float iv = in_s[ic][sy * 4 + i + dy][sx + dx];
                        u64 iv2 = pack2(iv, iv);
#pragma unroll
                        for (int j = 0; j < 8; j++)
                            fma2(acc[i][j], iv2, wv[j]);
                    }
                }
            }
        }
    }

#pragma unroll
    for (int i = 0; i < 4; i++) {
        int y = y0 + sy * 4 + i;
        int x = x0 + sx;
        if (y < H && x < W) {
#pragma unroll
            for (int j = 0; j < 8; j++) {
                int oc = ocg * 16 + 2 * j;
                float2 v = unpack2(acc[i][j]);
                float r0 = fmaxf(v.x + bias[oc], 0.0f);
                float r1 = fmaxf(v.y + bias[oc + 1], 0.0f);
                out[(((size_t)b * OC + oc)     * H + y) * W + x] = r0;
                out[(((size_t)b * OC + oc + 1) * H + y) * W + x] = r1;
            }
        }
    }
}

// ---------------------------------------------------------------------------
// Kernel 4: 5x5 SAME conv, IC=32 -> OC=1, bias, no relu.
// ---------------------------------------------------------------------------
__global__ __launch_bounds__(256)
void conv5x5_ic32_oc1(const float* __restrict__ in,
                      const float* __restrict__ w,
                      const float* __restrict__ bias,
                      float* __restrict__ out,
                      int H, int W)
{
    const int TW = 32, TH = 8, ICC = 8, IC = 32;
    __shared__ float in_s[ICC][TH + 4][TW + 4];
    __shared__ float w_s[ICC][25];

    int b  = blockIdx.z;
    int x0 = blockIdx.x * TW;
    int y0 = blockIdx.y * TH;
    int tid = threadIdx.x;
    int sx = tid & 31;
    int sy = tid >> 5;            // 0..7

    float acc = 0.0f;
    for (int cc = 0; cc < IC; cc += ICC) {
        __syncthreads();
        const float* inb = in + ((size_t)b * IC + cc) * H * W;
        for (int t = tid; t < ICC * (TH + 4) * (TW + 4); t += 256) {
            int ic  = t / ((TH + 4) * (TW + 4));
            int rem = t - ic * (TH + 4) * (TW + 4);
            int r = rem / (TW + 4);
            int c = rem - r * (TW + 4);
            int gy = y0 - 2 + r;
            int gx = x0 - 2 + c;
            float vv = 0.0f;
            if (gy >= 0 && gy < H && gx >= 0 && gx < W)
                vv = inb[(size_t)ic * H * W + (size_t)gy * W + gx];
            in_s[ic][r][c] = vv;
        }
        for (int t = tid; t < ICC * 25; t += 256)
            w_s[t / 25][t % 25] = w[(size_t)(cc + t / 25) * 25 + (t % 25)];
        __syncthreads();

#pragma unroll 1
        for (int ic = 0; ic < ICC; ic++) {
#pragma unroll
            for (int dy = 0; dy < 5; dy++)
#pragma unroll
                for (int dx = 0; dx < 5; dx++)
                    acc = fmaf(in_s[ic][sy + dy][sx + dx], w_s[ic][dy * 5 + dx], acc);
        }
    }

    int y = y0 + sy, x = x0 + sx;
    if (y < H && x < W)
        out[((size_t)b * H + y) * W + x] = acc + bias[0];
}

// ---------------------------------------------------------------------------
// Orchestration
// ---------------------------------------------------------------------------
extern "C" void kernel_launch(void* const* d_in, const int* in_sizes, int n_in,
                              void* d_out, int out_size)
{
    const float* x        = (const float*)d_in[0];
    const float* elev0    = (const float*)d_in[1];
    const float* elev1    = (const float*)d_in[2];
    const int*   psi_idx1 = (const int*)  d_in[3];
    const float* psi_val1 = (const float*)d_in[4];
    const float* w1       = (const float*)d_in[5];
    const float* b1       = (const float*)d_in[6];
    const float* cw2_1    = (const float*)d_in[7];
    const float* cb2_1    = (const float*)d_in[8];
    const float* cw3_1    = (const float*)d_in[9];
    const float* cb3_1    = (const float*)d_in[10];
    const int*   psi_idx2 = (const int*)  d_in[11];
    const float* psi_val2 = (const float*)d_in[12];
    const float* w2       = (const float*)d_in[13];
    const float* b2       = (const float*)d_in[14];
    const float* cw2_2    = (const float*)d_in[15];
    const float* cb2_2    = (const float*)d_in[16];
    const float* cw3_2    = (const float*)d_in[17];
    const float* cb3_2    = (const float*)d_in[18];
    float* out = (float*)d_out;

    float* scratch = nullptr;
    cudaGetSymbolAddress((void**)&scratch, g_scratch);
    float* bufA  = scratch + OFF_A;    // disco output
    float* bufB2 = scratch + OFF_B2;   // conv2 output
    float* bufH  = scratch + OFF_H;    // concat input
    float* bufY1 = scratch + OFF_Y1;   // stage1 final

    // ---------------- stage 1: 90x180 -> 180x360 ----------------
    {
        const int H = 180, W = 360, P = H * W;
        int total = B_ * H * W;
        upsample_concat_kernel<<<(total + 255) / 256, 256>>>(x, elev0, bufH, 90, 180);
        disco_kernel<<<(P + 255) / 256, 256>>>(bufH, psi_idx1, psi_val1, w1, b1, bufA, P);
        dim3 g2((W + 31) / 32, (H + 15) / 16, B_);
        conv5x5_ic64_oc32_relu<<<g2, 256>>>(bufA, cw2_1, cb2_1, bufB2, H, W);
        dim3 g3((W + 31) / 32, (H + 7) / 8, B_);
        conv5x5_ic32_oc1<<<g3, 256>>>(bufB2, cw3_1, cb3_1, bufY1, H, W);
    }
    // ---------------- stage 2: 180x360 -> 360x720 ----------------
    {
        const int H = 360, W = 720, P = H * W;
        int total = B_ * H * W;
        upsample_concat_kernel<<<(total + 255) / 256, 256>>>(bufY1, elev1, bufH, 180, 360);
        disco_kernel<<<(P + 255) / 256, 256>>>(bufH, psi_idx2, psi_val2, w2, b2, bufA, P);
        dim3 g2((W + 31) / 32, (H + 15) / 16, B_);
        conv5x5_ic64_oc32_relu<<<g2, 256>>>(bufA, cw2_2, cb2_2, bufB2, H, W);
        dim3 g3((W + 31) / 32, (H + 7) / 8, B_);
        conv5x5_ic32_oc1<<<g3, 256>>>(bufB2, cw3_2, cb3_2, out, H, W);
    }
}

// round 6
// speedup vs baseline: 3.1576x; 3.1576x over previous
#include <cuda_runtime.h>
#include <cuda_fp16.h>
#include <cstdint>
#include <cstddef>

// ===========================================================================
// DeepSDSphere R6: conv2 (5x5, 64->32) as implicit GEMM on legacy warp-level
// fp16 tensor cores (ldmatrix + mma.sync.m16n8k16, sm_80 PTX -> HMMA on
// sm_103). disco writes padded NHWC fp16; weights pre-converted fp16.
// ===========================================================================

#define B_   4
#define F_   64

// ---------------- scratch layout (floats) -----------------------------------
#define SZ_NHWCH (4ull*364ull*724ull*64ull/2ull)   // fp16 NHWC as float count
#define SZ_B2    (4ull*32ull*360ull*720ull)
#define SZ_H     (4ull*2ull*360ull*720ull)
#define SZ_Y1    (4ull*180ull*360ull)
#define SZ_WH    (25ull*64ull*32ull/2ull)          // fp16 weights as float count
#define OFF_NHWCH 0ull
#define OFF_B2    (OFF_NHWCH + SZ_NHWCH)
#define OFF_H     (OFF_B2 + SZ_B2)
#define OFF_Y1    (OFF_H + SZ_H)
#define OFF_WH    (OFF_Y1 + SZ_Y1)
#define SCRATCH_FLOATS (OFF_WH + SZ_WH)

__device__ __align__(1024) float g_scratch[SCRATCH_FLOATS];

__device__ __forceinline__ uint32_t smem_u32(const void* p) {
    uint32_t a;
    asm("{ .reg .u64 t; cvta.to.shared.u64 t, %1; cvt.u32.u64 %0, t; }"
        : "=r"(a) : "l"(p));
    return a;
}

// ---------------------------------------------------------------------------
// bilinear 2x upsample (half-pixel) + concat -> (B,2,H2,W2) NCHW fp32
// ---------------------------------------------------------------------------
__global__ void upsample_concat_kernel(const float* __restrict__ x,
                                       const float* __restrict__ elev,
                                       float* __restrict__ out,
                                       int Hin, int Win)
{
    int H2 = Hin * 2, W2 = Win * 2;
    int total = B_ * H2 * W2;
    int idx = blockIdx.x * blockDim.x + threadIdx.x;
    if (idx >= total) return;
    int j = idx % W2;
    int t = idx / W2;
    int i = t % H2;
    int b = t / H2;

    float sy = (i + 0.5f) * 0.5f - 0.5f;
    sy = fminf(fmaxf(sy, 0.0f), (float)(Hin - 1));
    int r0 = (int)floorf(sy);
    int r1 = min(r0 + 1, Hin - 1);
    float ty = sy - (float)r0;

    float sx = (j + 0.5f) * 0.5f - 0.5f;
    sx = fminf(fmaxf(sx, 0.0f), (float)(Win - 1));
    int c0 = (int)floorf(sx);
    int c1 = min(c0 + 1, Win - 1);
    float tx = sx - (float)c0;

    const float* xb = x + (size_t)b * Hin * Win;
    float v00 = xb[r0 * Win + c0];
    float v01 = xb[r0 * Win + c1];
    float v10 = xb[r1 * Win + c0];
    float v11 = xb[r1 * Win + c1];
    float left  = v00 * (1.0f - ty) + v10 * ty;
    float right = v01 * (1.0f - ty) + v11 * ty;
    float v = left * (1.0f - tx) + right * tx;

    size_t plane = (size_t)H2 * W2;
    out[((size_t)b * 2 + 0) * plane + (size_t)i * W2 + j] = v;
    out[((size_t)b * 2 + 1) * plane + (size_t)i * W2 + j] =
        elev[(size_t)b * plane + (size_t)i * W2 + j];
}

// ---------------------------------------------------------------------------
// zero 2-wide borders of padded NHWC fp16 buffer (64ch/pixel = 128B)
// ---------------------------------------------------------------------------
__global__ void pad_zero_h_kernel(__half* __restrict__ nhwc, int Hp, int Wp)
{
    int i = blockIdx.x * 256 + threadIdx.x;
    int total = B_ * Hp * Wp;
    if (i >= total) return;
    int x = i % Wp;
    int y = (i / Wp) % Hp;
    if (y >= 2 && y < Hp - 2 && x >= 2 && x < Wp - 2) return;
    uint4 z = make_uint4(0, 0, 0, 0);
    uint4* p = (uint4*)(nhwc + (size_t)i * 64);
#pragma unroll
    for (int k = 0; k < 8; k++) p[k] = z;
}

// ---------------------------------------------------------------------------
// disco conv + bias + relu -> padded NHWC fp16
// ---------------------------------------------------------------------------
__global__ __launch_bounds__(256)
void disco_kernel(const float* __restrict__ h,
                  const int*   __restrict__ idx,
                  const float* __restrict__ val,
                  const float* __restrict__ w,
                  const float* __restrict__ bias,
                  __half* __restrict__ nhwc,
                  int P, int W, int Hp, int Wp)
{
    __shared__ float w_s[F_ * 18];
    __shared__ float b_s[F_];
    for (int t = threadIdx.x; t < F_ * 18; t += 256) w_s[t] = w[t];
    if (threadIdx.x < F_) b_s[threadIdx.x] = bias[threadIdx.x];
    __syncthreads();

    int p = blockIdx.x * 256 + threadIdx.x;
    if (p >= P) return;
    int px = p % W, py = p / W;

    int id[8];
    const int4* ip = reinterpret_cast<const int4*>(idx + (size_t)p * 8);
    int4 ia = ip[0], ib = ip[1];
    id[0]=ia.x; id[1]=ia.y; id[2]=ia.z; id[3]=ia.w;
    id[4]=ib.x; id[5]=ib.y; id[6]=ib.z; id[7]=ib.w;

    float v[9][8];
#pragma unroll
    for (int k = 0; k < 9; k++) {
        const float4* vp = reinterpret_cast<const float4*>(val + ((size_t)k * P + p) * 8);
        float4 a = vp[0], c = vp[1];
        v[k][0]=a.x; v[k][1]=a.y; v[k][2]=a.z; v[k][3]=a.w;
        v[k][4]=c.x; v[k][5]=c.y; v[k][6]=c.z; v[k][7]=c.w;
    }

    for (int b = 0; b < B_; b++) {
        const float* h0 = h + (size_t)(b * 2 + 0) * P;
        const float* h1 = h + (size_t)(b * 2 + 1) * P;
        float g0[8], g1[8];
#pragma unroll
        for (int n = 0; n < 8; n++) { g0[n] = h0[id[n]]; g1[n] = h1[id[n]]; }

        float z0[9], z1[9];
#pragma unroll
        for (int k = 0; k < 9; k++) {
            float s0 = 0.0f, s1 = 0.0f;
#pragma unroll
            for (int n = 0; n < 8; n++) {
                s0 = fmaf(g0[n], v[k][n], s0);
                s1 = fmaf(g1[n], v[k][n], s1);
            }
            z0[k] = s0; z1[k] = s1;
        }

        // output pixel base: 64 halves = 8 x uint4
        uint4* ob = (uint4*)(nhwc +
            (((size_t)b * Hp + (py + 2)) * Wp + (px + 2)) * 64);
        for (int o8 = 0; o8 < 8; o8++) {
            __half hv[8];
#pragma unroll
            for (int q = 0; q < 8; q++) {
                int o = o8 * 8 + q;
                const float* wo = &w_s[o * 18];
                float a = b_s[o];
#pragma unroll
                for (int k = 0; k < 9; k++)
                    a = fmaf(z0[k], wo[k], fmaf(z1[k], wo[9 + k], a));
                hv[q] = __float2half_rn(fmaxf(a, 0.0f));
            }
            ob[o8] = *(uint4*)hv;
        }
    }
}

// ---------------------------------------------------------------------------
// weight transform: (32oc,64ic,5,5) fp32 -> fp16 [tap][ic][oc]
// ---------------------------------------------------------------------------
__global__ void wtransform_kernel(const float* __restrict__ w,
                                  __half* __restrict__ wh)
{
    int i = blockIdx.x * 256 + threadIdx.x;
    if (i >= 25 * 64 * 32) return;
    int tap = i / 2048;
    int r = i % 2048;
    int ic = r >> 5;
    int oc = r & 31;
    wh[i] = __float2half_rn(w[((size_t)oc * 64 + ic) * 25 + tap]);
}

// ---------------------------------------------------------------------------
// conv2 via warp-level fp16 mma: D[128px,32oc] fp32 = sum of 25 shifted GEMMs.
// 256 thr = 8 warps; warp m-tile = 16 px. Per dy: stage ext-row A (132x64 fp16,
// XOR-swizzled 16B granules) + 5 B taps (64x32 fp16, 80B row stride).
// ---------------------------------------------------------------------------
__global__ __launch_bounds__(256)
void conv2_mma(const __half* __restrict__ nhwc, const __half* __restrict__ wh,
               const float* __restrict__ bias, float* __restrict__ out,
               int H, int W)
{
    __shared__ __align__(16) char As[132 * 128];    // 16,896 B
    __shared__ __align__(16) char Bs[5 * 64 * 80];  // 25,600 B

    const int Hp = H + 4, Wp = W + 4;
    int b = blockIdx.z, y = blockIdx.y;
    int x0 = blockIdx.x * 128;
    if (x0 > W - 128) x0 = W - 128;
    int tid = threadIdx.x;
    int warp = tid >> 5, lane = tid & 31;

    uint32_t As_b = smem_u32(As);
    uint32_t Bs_b = smem_u32(Bs);

    float acc[4][4];   // 4 n-chunks (8 oc each) x 4 regs
#pragma unroll
    for (int j = 0; j < 4; j++)
#pragma unroll
        for (int q = 0; q < 4; q++) acc[j][q] = 0.0f;

    for (int dy = 0; dy < 5; dy++) {
        __syncthreads();
        // A: one contiguous padded row segment, 132 px x 64 ch fp16 = 16,896 B
        const uint4* srcA = (const uint4*)(nhwc +
            ((size_t)(b * Hp + y + dy) * Wp + x0) * 64);
#pragma unroll
        for (int i = tid; i < 1056; i += 256) {
            int p = i >> 3, g = i & 7;
            *(uint4*)(As + p * 128 + ((g ^ (p & 7)) << 4)) = srcA[i];
        }
        // B: taps dy*5 .. dy*5+4, each [64k][32n] fp16 -> 80B-stride rows
        const uint4* srcB = (const uint4*)(wh + (size_t)dy * 5 * 2048);
#pragma unroll
        for (int i = tid; i < 1280; i += 256) {
            int tap5 = i >> 8, k = (i >> 2) & 63, g = i & 3;
            *(uint4*)(Bs + tap5 * 5120 + k * 80 + g * 16) = srcB[i];
        }
        __syncthreads();

#pragma unroll
        for (int dx = 0; dx < 5; dx++) {
#pragma unroll
            for (int ks = 0; ks < 4; ks++) {
                // A fragment: rows m = warp*16+dx+(lane&15), k-granule ks*2+(lane>>4)
                uint32_t a0, a1, a2, a3;
                {
                    int r = warp * 16 + dx + (lane & 15);
                    int g = ks * 2 + (lane >> 4);
                    uint32_t addr = As_b + r * 128 + ((g ^ (r & 7)) << 4);
                    asm volatile(
                        "ldmatrix.sync.aligned.m8n8.x4.shared.b16 {%0,%1,%2,%3}, [%4];"
                        : "=r"(a0), "=r"(a1), "=r"(a2), "=r"(a3) : "r"(addr));
                }
#pragma unroll
                for (int j2 = 0; j2 < 2; j2++) {
                    uint32_t b0, b1, b2, b3;
                    {
                        int k = ks * 16 + (lane & 15);
                        int g = j2 * 2 + (lane >> 4);
                        uint32_t addr = Bs_b + dx * 5120 + k * 80 + g * 16;
                        asm volatile(
                            "ldmatrix.sync.aligned.m8n8.x4.trans.shared.b16 {%0,%1,%2,%3}, [%4];"
                            : "=r"(b0), "=r"(b1), "=r"(b2), "=r"(b3) : "r"(addr));
                    }
                    float* d0 = acc[j2 * 2 + 0];
                    asm volatile(
                        "mma.sync.aligned.m16n8k16.row.col.f32.f16.f16.f32 "
                        "{%0,%1,%2,%3}, {%4,%5,%6,%7}, {%8,%9}, {%0,%1,%2,%3};"
                        : "+f"(d0[0]), "+f"(d0[1]), "+f"(d0[2]), "+f"(d0[3])
                        : "r"(a0), "r"(a1), "r"(a2), "r"(a3), "r"(b0), "r"(b1));
                    float* d1 = acc[j2 * 2 + 1];
                    asm volatile(
                        "mma.sync.aligned.m16n8k16.row.col.f32.f16.f16.f32 "
                        "{%0,%1,%2,%3}, {%4,%5,%6,%7}, {%8,%9}, {%0,%1,%2,%3};"
                        : "+f"(d1[0]), "+f"(d1[1]), "+f"(d1[2]), "+f"(d1[3])
                        : "r"(a0), "r"(a1), "r"(a2), "r"(a3), "r"(b2), "r"(b3));
                }
            }
        }
    }

    // epilogue: D row = output x0+m, col = oc. Thread holds (r0,c0),(r0,c0+1),
    // (r0+8,c0),(r0+8,c0+1) per n-chunk, r0 = lane>>2, c0 = 2*(lane&3).
    int r0 = lane >> 2, c0 = (lane & 3) * 2;
    int xbase = x0 + warp * 16;
#pragma unroll
    for (int j = 0; j < 4; j++) {
        int oc0 = j * 8 + c0;
        float bs0 = __ldg(&bias[oc0]), bs1 = __ldg(&bias[oc0 + 1]);
        size_t p0 = (((size_t)b * 32 + oc0)     * H + y) * W;
        size_t p1 = (((size_t)b * 32 + oc0 + 1) * H + y) * W;
        out[p0 + xbase + r0]     = fmaxf(acc[j][0] + bs0, 0.0f);
        out[p1 + xbase + r0]     = fmaxf(acc[j][1] + bs1, 0.0f);
        out[p0 + xbase + r0 + 8] = fmaxf(acc[j][2] + bs0, 0.0f);
        out[p1 + xbase + r0 + 8] = fmaxf(acc[j][3] + bs1, 0.0f);
    }
}

// ---------------------------------------------------------------------------
// conv3: 5x5, IC=32 -> OC=1 (proven kernel, unchanged)
// ---------------------------------------------------------------------------
__global__ __launch_bounds__(256)
void conv5x5_ic32_oc1(const float* __restrict__ in,
                      const float* __restrict__ w,
                      const float* __restrict__ bias,
                      float* __restrict__ out,
                      int H, int W)
{
    const int TW = 32, TH = 8, ICC = 8, IC = 32;
    __shared__ float in_s[ICC][TH + 4][TW + 4];
    __shared__ float w_s[ICC][25];

    int b  = blockIdx.z;
    int x0 = blockIdx.x * TW;
    int y0 = blockIdx.y * TH;
    int tid = threadIdx.x;
    int sx = tid & 31;
    int sy = tid >> 5;

    float acc = 0.0f;
    for (int cc = 0; cc < IC; cc += ICC) {
        __syncthreads();
        const float* inb = in + ((size_t)b * IC + cc) * H * W;
        for (int t = tid; t < ICC * (TH + 4) * (TW + 4); t += 256) {
            int ic  = t / ((TH + 4) * (TW + 4));
            int rem = t - ic * ((TH + 4) * (TW + 4));
            int r = rem / (TW + 4);
            int c = rem - r * (TW + 4);
            int gy = y0 - 2 + r;
            int gx = x0 - 2 + c;
            float vv = 0.0f;
            if (gy >= 0 && gy < H && gx >= 0 && gx < W)
                vv = inb[(size_t)ic * H * W + (size_t)gy * W + gx];
            in_s[ic][r][c] = vv;
        }
        for (int t = tid; t < ICC * 25; t += 256)
            w_s[t / 25][t % 25] = w[(size_t)(cc + t / 25) * 25 + (t % 25)];
        __syncthreads();

#pragma unroll 1
        for (int ic = 0; ic < ICC; ic++) {
#pragma unroll
            for (int dy = 0; dy < 5; dy++)
#pragma unroll
                for (int dx = 0; dx < 5; dx++)
                    acc = fmaf(in_s[ic][sy + dy][sx + dx], w_s[ic][dy * 5 + dx], acc);
        }
    }

    int y = y0 + sy, x = x0 + sx;
    if (y < H && x < W)
        out[((size_t)b * H + y) * W + x] = acc + bias[0];
}

// ---------------------------------------------------------------------------
// Orchestration
// ---------------------------------------------------------------------------
extern "C" void kernel_launch(void* const* d_in, const int* in_sizes, int n_in,
                              void* d_out, int out_size)
{
    const float* x        = (const float*)d_in[0];
    const float* elev0    = (const float*)d_in[1];
    const float* elev1    = (const float*)d_in[2];
    const int*   psi_idx1 = (const int*)  d_in[3];
    const float* psi_val1 = (const float*)d_in[4];
    const float* w1       = (const float*)d_in[5];
    const float* b1       = (const float*)d_in[6];
    const float* cw2_1    = (const float*)d_in[7];
    const float* cb2_1    = (const float*)d_in[8];
    const float* cw3_1    = (const float*)d_in[9];
    const float* cb3_1    = (const float*)d_in[10];
    const int*   psi_idx2 = (const int*)  d_in[11];
    const float* psi_val2 = (const float*)d_in[12];
    const float* w2       = (const float*)d_in[13];
    const float* b2       = (const float*)d_in[14];
    const float* cw2_2    = (const float*)d_in[15];
    const float* cb2_2    = (const float*)d_in[16];
    const float* cw3_2    = (const float*)d_in[17];
    const float* cb3_2    = (const float*)d_in[18];
    float* out = (float*)d_out;

    float* scratch = nullptr;
    cudaGetSymbolAddress((void**)&scratch, g_scratch);
    __half* nhwcH = (__half*)(scratch + OFF_NHWCH);
    float*  bufB2 = scratch + OFF_B2;
    float*  bufH  = scratch + OFF_H;
    float*  bufY1 = scratch + OFF_Y1;
    __half* bufWH = (__half*)(scratch + OFF_WH);

    // ---------------- stage 1: 90x180 -> 180x360 ----------------
    {
        const int H = 180, W = 360, P = H * W, Hp = H + 4, Wp = W + 4;
        int total = B_ * H * W;
        upsample_concat_kernel<<<(total + 255) / 256, 256>>>(x, elev0, bufH, 90, 180);
        pad_zero_h_kernel<<<(B_ * Hp * Wp + 255) / 256, 256>>>(nhwcH, Hp, Wp);
        disco_kernel<<<(P + 255) / 256, 256>>>(bufH, psi_idx1, psi_val1, w1, b1,
                                               nhwcH, P, W, Hp, Wp);
        wtransform_kernel<<<200, 256>>>(cw2_1, bufWH);
        dim3 g2((W + 127) / 128, H, B_);
        conv2_mma<<<g2, 256>>>(nhwcH, bufWH, cb2_1, bufB2, H, W);
        dim3 g3((W + 31) / 32, (H + 7) / 8, B_);
        conv5x5_ic32_oc1<<<g3, 256>>>(bufB2, cw3_1, cb3_1, bufY1, H, W);
    }
    // ---------------- stage 2: 180x360 -> 360x720 ----------------
    {
        const int H = 360, W = 720, P = H * W, Hp = H + 4, Wp = W + 4;
        int total = B_ * H * W;
        upsample_concat_kernel<<<(total + 255) / 256, 256>>>(bufY1, elev1, bufH, 180, 360);
        pad_zero_h_kernel<<<(B_ * Hp * Wp + 255) / 256, 256>>>(nhwcH, Hp, Wp);
        disco_kernel<<<(P + 255) / 256, 256>>>(bufH, psi_idx2, psi_val2, w2, b2,
                                               nhwcH, P, W, Hp, Wp);
        wtransform_kernel<<<200, 256>>>(cw2_2, bufWH);
        dim3 g2((W + 127) / 128, H, B_);
        conv2_mma<<<g2, 256>>>(nhwcH, bufWH, cb2_2, bufB2, H, W);
        dim3 g3((W + 31) / 32, (H + 7) / 8, B_);
        conv5x5_ic32_oc1<<<g3, 256>>>(bufB2, cw3_2, cb3_2, out, H, W);
    }
}